// round 11
// baseline (speedup 1.0000x reference)
#include <cuda_runtime.h>
#include <cstdint>

// Problem constants
constexpr int C   = 128;
constexpr int CF  = 16;
constexpr int N   = 256;
constexpr int K   = 15;
constexpr int TPB = 1024;  // (pixel, quarter)

constexpr int XO_PITCH   = 132;  // [N][C] patch tile; float4 conflict-free (33 quads, odd)
constexpr int XN_PITCH   = 20;   // [N][18] normalized feats
constexpr int AC_PITCH   = 20;   // [N][18] pre-norm feats
constexpr int CAND_PITCH = 20;   // candidate bytes per row

// shared memory layout (bytes)
constexpr int OFF_INV   = 0;                              // 256 double  = 2048
constexpr int OFF_XO    = 2048;                           // 256*132*4   = 135168
constexpr int OFF_FW    = OFF_XO + N * XO_PITCH * 4;      // 8192
constexpr int OFF_FB    = OFF_FW + CF * C * 4;            // 64
constexpr int OFF_XNF   = OFF_FB + CF * 4;                // 20480
constexpr int OFF_ACC   = OFF_XNF + N * XN_PITCH * 4;     // 20480
constexpr int OFF_UNION = OFF_ACC + N * AC_PITCH * 4;     // buf1 36864 | simk 36864 | stg 32768
constexpr int OFF_CAND  = OFF_UNION + 36864;              // 5120
constexpr int SMEM_BYTES = OFF_CAND + N * CAND_PITCH;     // 228416 B

// monotone float<->u32 (order-preserving)
__device__ __forceinline__ uint32_t fmono(float f) {
    uint32_t b = __float_as_uint(f);
    return (b & 0x80000000u) ? ~b : (b | 0x80000000u);
}
// monotone double<->u64
__device__ __forceinline__ uint64_t dmono(double d) {
    uint64_t b = (uint64_t)__double_as_longlong(d);
    return (b & 0x8000000000000000ull) ? ~b : (b | 0x8000000000000000ull);
}
__device__ __forceinline__ double dunmono(uint64_t u) {
    uint64_t b = (u & 0x8000000000000000ull) ? (u & 0x7FFFFFFFFFFFFFFFull) : ~u;
    return __longlong_as_double((long long)b);
}

// staging swizzle: conflict-free for channel-lane writes AND pixel-lane reads
__device__ __forceinline__ int stg_off(int c, int px) {
    return c * 64 + ((px + (c >> 2) + 8 * (c & 3)) & 63);
}

__global__ void __launch_bounds__(TPB, 1)
gnn_local_cluster_kernel(const float* __restrict__ x_in,
                         const float* __restrict__ f_w,
                         const float* __restrict__ f_b,
                         const float* __restrict__ edge_alpha,
                         const float* __restrict__ edge_beta,
                         float* __restrict__ out)
{
    extern __shared__ char smraw[];
    double*   invn = reinterpret_cast<double*>(smraw + OFF_INV);    // [N] 1/norm fp64
    float*    xo   = reinterpret_cast<float*>(smraw + OFF_XO);      // [N][132]
    float*    fw   = reinterpret_cast<float*>(smraw + OFF_FW);      // [16][128]
    float*    fb   = reinterpret_cast<float*>(smraw + OFF_FB);      // [16]
    float*    xnf  = reinterpret_cast<float*>(smraw + OFF_XNF);     // [N][20] normalized
    float*    accf = reinterpret_cast<float*>(smraw + OFF_ACC);     // [N][20] pre-norm; later weights
    uint32_t* buf1 = reinterpret_cast<uint32_t*>(smraw + OFF_UNION);// [512][18] merge buffers
    uint64_t* simk = reinterpret_cast<uint64_t*>(smraw + OFF_UNION);// [256][18] rerank keys
    float*    stg  = reinterpret_cast<float*>(smraw + OFF_UNION);   // [128][64] gather staging
    uint8_t*  cand = reinterpret_cast<uint8_t*>(smraw + OFF_CAND);  // [256][20] candidate rows

    const int p   = blockIdx.x;
    const int b   = p / 49;
    const int wg  = (p / 7) % 7;
    const int hg  = p % 7;
    const int tid = threadIdx.x;
    const int n   = tid & 255;     // pixel
    const int q   = tid >> 8;      // quarter id (0..3)

    const int gbase = ((b * C * 112) + wg * 16) * 112 + hg * 16;

    // ---- load weights + patch tile ----
    for (int idx = tid; idx < CF * C; idx += TPB) fw[idx] = f_w[idx];
    if (tid < CF) fb[tid] = f_b[tid];
    for (int idx = tid; idx < C * N; idx += TPB) {
        int c = idx >> 8;
        int nn = idx & 255;
        int i = nn >> 4, j = nn & 15;
        xo[nn * XO_PITCH + c] = x_in[gbase + c * (112 * 112) + i * 112 + j];
    }
    __syncthreads();

    // ---- conv: thread (n,q) computes channels q*4..q*4+3 of pixel n ----
    // float4 loads both sides; per-channel: c ascending, FMA from 0, bias after
    // — bitwise-identical features to R6/R8/R10.
    {
        float a0 = 0.f, a1 = 0.f, a2 = 0.f, a3 = 0.f;
        const float4* xr4 = reinterpret_cast<const float4*>(xo + n * XO_PITCH);
        const float*  fwq = fw + (q * 4) * C;
        #pragma unroll 8
        for (int c4 = 0; c4 < 32; ++c4) {
            float4 xv = xr4[c4];
            float4 w0 = *reinterpret_cast<const float4*>(fwq +           c4 * 4);
            float4 w1 = *reinterpret_cast<const float4*>(fwq + C       + c4 * 4);
            float4 w2 = *reinterpret_cast<const float4*>(fwq + 2 * C   + c4 * 4);
            float4 w3 = *reinterpret_cast<const float4*>(fwq + 3 * C   + c4 * 4);
            a0 = __fmaf_rn(xv.x, w0.x, a0); a0 = __fmaf_rn(xv.y, w0.y, a0);
            a0 = __fmaf_rn(xv.z, w0.z, a0); a0 = __fmaf_rn(xv.w, w0.w, a0);
            a1 = __fmaf_rn(xv.x, w1.x, a1); a1 = __fmaf_rn(xv.y, w1.y, a1);
            a1 = __fmaf_rn(xv.z, w1.z, a1); a1 = __fmaf_rn(xv.w, w1.w, a1);
            a2 = __fmaf_rn(xv.x, w2.x, a2); a2 = __fmaf_rn(xv.y, w2.y, a2);
            a2 = __fmaf_rn(xv.z, w2.z, a2); a2 = __fmaf_rn(xv.w, w2.w, a2);
            a3 = __fmaf_rn(xv.x, w3.x, a3); a3 = __fmaf_rn(xv.y, w3.y, a3);
            a3 = __fmaf_rn(xv.z, w3.z, a3); a3 = __fmaf_rn(xv.w, w3.w, a3);
        }
        float4 o;
        o.x = __fadd_rn(a0, fb[q * 4 + 0]);
        o.y = __fadd_rn(a1, fb[q * 4 + 1]);
        o.z = __fadd_rn(a2, fb[q * 4 + 2]);
        o.w = __fadd_rn(a3, fb[q * 4 + 3]);
        *reinterpret_cast<float4*>(accf + n * AC_PITCH + q * 4) = o;
    }
    __syncthreads();

    // ---- norm (q==0): fp64-exact inverse norm; fp32 normalized feats ----
    if (q == 0) {
        const int i = n >> 4, j = n & 15;
        const float sd    = __fsqrt_rn(__fdiv_rn(5440.0f, 255.0f));
        const float denom = __fadd_rn(sd, 1e-5f);
        const float g0 = __fdiv_rn((float)i - 7.5f, denom);
        const float g1 = __fdiv_rn((float)j - 7.5f, denom);
        float* ar = accf + n * AC_PITCH;
        ar[16] = g0; ar[17] = g1; ar[18] = 0.0f; ar[19] = 0.0f;

        double ss = 0.0;
        #pragma unroll
        for (int d = 0; d < CF; ++d) ss = fma((double)ar[d], (double)ar[d], ss);
        ss = fma((double)g0, (double)g0, ss);
        ss = fma((double)g1, (double)g1, ss);
        double nd = sqrt(ss);
        if (nd < 1e-8) nd = 1e-8;
        double inv = 1.0 / nd;
        invn[n] = inv;
        const float rinv = (float)inv;

        float* xw = xnf + n * XN_PITCH;
        #pragma unroll
        for (int d = 0; d < CF; ++d) xw[d] = ar[d] * rinv;
        xw[16] = g0 * rinv; xw[17] = g1 * rinv; xw[18] = 0.0f; xw[19] = 0.0f;
    }
    __syncthreads();

    // ---- pass 1: row n vs candidates [q*64, q*64+64), packed top-16 ----
    uint32_t kb[16];
    {
        float rreg[18];
        const float* xr = xnf + n * XN_PITCH;
        #pragma unroll
        for (int d = 0; d < 18; ++d) rreg[d] = xr[d];

        #pragma unroll
        for (int k = 0; k < 16; ++k) kb[k] = 0;

        const int mbase = q * 64;
        for (int mm = 0; mm < 64; ++mm) {
            const int m = mbase + mm;
            const float4* xm4 = reinterpret_cast<const float4*>(xnf + m * XN_PITCH);
            float4 v0 = xm4[0], v1 = xm4[1], v2 = xm4[2], v3 = xm4[3];  // broadcast
            float2 v4 = *reinterpret_cast<const float2*>(xnf + m * XN_PITCH + 16);
            float s0 = 0.f, s1 = 0.f, s2 = 0.f, s3 = 0.f;
            s0 = __fmaf_rn(rreg[0],  v0.x, s0); s1 = __fmaf_rn(rreg[1],  v0.y, s1);
            s2 = __fmaf_rn(rreg[2],  v0.z, s2); s3 = __fmaf_rn(rreg[3],  v0.w, s3);
            s0 = __fmaf_rn(rreg[4],  v1.x, s0); s1 = __fmaf_rn(rreg[5],  v1.y, s1);
            s2 = __fmaf_rn(rreg[6],  v1.z, s2); s3 = __fmaf_rn(rreg[7],  v1.w, s3);
            s0 = __fmaf_rn(rreg[8],  v2.x, s0); s1 = __fmaf_rn(rreg[9],  v2.y, s1);
            s2 = __fmaf_rn(rreg[10], v2.z, s2); s3 = __fmaf_rn(rreg[11], v2.w, s3);
            s0 = __fmaf_rn(rreg[12], v3.x, s0); s1 = __fmaf_rn(rreg[13], v3.y, s1);
            s2 = __fmaf_rn(rreg[14], v3.z, s2); s3 = __fmaf_rn(rreg[15], v3.w, s3);
            s0 = __fmaf_rn(rreg[16], v4.x, s0); s1 = __fmaf_rn(rreg[17], v4.y, s1);
            float s = __fadd_rn(__fadd_rn(s0, s1), __fadd_rn(s2, s3));

            uint32_t key = (fmono(s) & 0xFFFFFF00u) | (uint32_t)(255 - m);
            if (key > kb[15]) {
                uint32_t v = key;
                #pragma unroll
                for (int k = 0; k < 16; ++k) {
                    uint32_t mx = (v > kb[k]) ? v : kb[k];
                    uint32_t mn = (v > kb[k]) ? kb[k] : v;
                    kb[k] = mx; v = mn;
                }
            }
        }
    }
    // stage 1: quarters 2,3 publish their lists
    if (q >= 2) {
        uint32_t* br = buf1 + (n * 2 + (q - 2)) * 18;
        #pragma unroll
        for (int k = 0; k < 16; ++k) br[k] = kb[k];
    }
    __syncthreads();

    // stage 2: quarters 0,1 merge own regs with partner list -> top-18
    if (q < 2) {
        uint32_t* br = buf1 + (n * 2 + q) * 18;
        uint32_t kb2[18];
        #pragma unroll
        for (int k = 0; k < 16; ++k) kb2[k] = kb[k];
        kb2[16] = 0; kb2[17] = 0;
        #pragma unroll
        for (int k = 0; k < 16; ++k) {
            uint32_t u = br[k];
            if (u <= kb2[17]) break;     // sorted desc: rest can't enter
            #pragma unroll
            for (int k2 = 0; k2 < 18; ++k2) {
                uint32_t mx = (u > kb2[k2]) ? u : kb2[k2];
                uint32_t mn = (u > kb2[k2]) ? kb2[k2] : u;
                kb2[k2] = mx; u = mn;
            }
        }
        #pragma unroll
        for (int k = 0; k < 18; ++k) br[k] = kb2[k];
    }
    __syncthreads();

    // stage 3: q==0 merges the two 18-lists -> 18-candidate superset
    if (q == 0) {
        const uint32_t* la = buf1 + (n * 2 + 0) * 18;
        const uint32_t* lb = buf1 + (n * 2 + 1) * 18;
        uint8_t* cr = cand + n * CAND_PITCH;
        int ia = 0, ib = 0;
        #pragma unroll
        for (int k = 0; k < 18; ++k) {       // ia+ib=k<=17 -> in-bounds
            uint32_t va = la[ia], vb = lb[ib];
            bool ta = (va >= vb);
            uint32_t v = ta ? va : vb;
            cr[k] = (uint8_t)(255u - (v & 0xFFu));
            ia += ta; ib += !ta;
        }
    }
    __syncthreads();   // buf1 dead; simk live from here

    // ---- df64 rerank: 18 candidates split 5/5/4/4 across quarters ----
    {
        float ra[20];
        {
            const float4* ar4 = reinterpret_cast<const float4*>(accf + n * AC_PITCH);
            #pragma unroll
            for (int e = 0; e < 5; ++e)
                reinterpret_cast<float4*>(ra)[e] = ar4[e];
        }
        const double inv_n = invn[n];
        const uint8_t* cr = cand + n * CAND_PITCH;
        const int t0 = (q < 2) ? q * 5 : 10 + (q - 2) * 4;
        const int tn = (q < 2) ? 5 : 4;

        #pragma unroll 1
        for (int tt = 0; tt < 5; ++tt) {
            if (tt >= tn) break;             // uniform per warp (q fixed)
            const int t = t0 + tt;
            const int m = (int)cr[t];
            // Dot2 (compensated fp32 dot) over candidate row, 4 terms at a time
            float sh = 0.0f, sl = 0.0f;
            const float4* am4 = reinterpret_cast<const float4*>(accf + m * AC_PITCH);
            #pragma unroll
            for (int e = 0; e < 5; ++e) {
                float4 av4 = am4[e];
                const float* avp = reinterpret_cast<const float*>(&av4);
                #pragma unroll
                for (int r = 0; r < 4; ++r) {
                    const int d = e * 4 + r;
                    if (d < 18) {
                        float av = ra[d], bv = avp[r];
                        float ph = __fmul_rn(av, bv);
                        float pl = __fmaf_rn(av, bv, -ph);
                        float t1 = __fadd_rn(sh, ph);
                        float zz = __fsub_rn(t1, sh);
                        float ee = __fadd_rn(__fsub_rn(sh, __fsub_rn(t1, zz)),
                                             __fsub_rn(ph, zz));
                        sh = t1;
                        sl = __fadd_rn(sl, __fadd_rn(ee, pl));
                    }
                }
            }
            double sim = ((double)sh + (double)sl) * inv_n * invn[m];
            simk[n * 18 + t] = (dmono(sim) & ~0xFFull) | (uint64_t)(255 - m);
        }
    }
    __syncthreads();

    // ---- top-15 select + sigmoid/softmax (q==0); weights into accf ----
    if (q == 0) {
        const uint64_t* sr = simk + n * 18;
        uint64_t top[K];
        #pragma unroll
        for (int k = 0; k < K; ++k) top[k] = 0;
        #pragma unroll
        for (int t = 0; t < 18; ++t) {
            uint64_t u = sr[t];
            if (u > top[K - 1]) {
                #pragma unroll
                for (int k = 0; k < K; ++k) {
                    uint64_t mx = (u > top[k]) ? u : top[k];
                    uint64_t mn = (u > top[k]) ? top[k] : u;
                    top[k] = mx; u = mn;
                }
            }
        }
        float sims[K]; int rows[K];
        #pragma unroll
        for (int k = 0; k < K; ++k) {
            rows[k] = 255 - (int)(top[k] & 0xFFull);
            sims[k] = (float)dunmono((top[k] & ~0xFFull) | 0x80ull);
        }

        const float alpha = edge_alpha[0];
        const float beta  = edge_beta[0];
        float wn_[K];
        float wmax = -1e30f;
        #pragma unroll
        for (int k = 0; k < K; ++k) {
            float z  = __fadd_rn(beta, __fmul_rn(alpha, sims[k]));
            float wv = __fdiv_rn(1.0f, __fadd_rn(1.0f, expf(-z)));
            wn_[k] = wv;
            wmax = fmaxf(wmax, wv);
        }
        float wsum = 0.0f;
        #pragma unroll
        for (int k = 0; k < K; ++k) {
            wn_[k] = expf(__fadd_rn(wn_[k], -wmax));
            wsum = __fadd_rn(wsum, wn_[k]);
        }
        float* wrow = accf + n * AC_PITCH;   // accf dead -> weights
        uint8_t* cr = cand + n * CAND_PITCH; // final neighbor rows
        #pragma unroll
        for (int k = 0; k < K; ++k) {
            wrow[k] = __fdiv_rn(wn_[k], wsum);
            cr[k]   = (uint8_t)rows[k];
        }
    }
    __syncthreads();   // simk dead; staging live from here

    // ---- gather: cooperative conflict-free loads + staged transpose ----
    {
        const int wid  = tid >> 5;       // 0..31
        const int lane = tid & 31;
        const float4* xo4 = reinterpret_cast<const float4*>(xo);

        #pragma unroll 1
        for (int g = 0; g < 4; ++g) {
            // each warp gathers 2 pixels; all lanes read the SAME neighbor row
            #pragma unroll
            for (int px = 0; px < 2; ++px) {
                const int pl = wid * 2 + px;      // 0..63
                const int n2 = g * 64 + pl;
                const float*   wrow = accf + n2 * AC_PITCH;
                const uint8_t* cr   = cand + n2 * CAND_PITCH;
                float4 o = make_float4(0.f, 0.f, 0.f, 0.f);
                #pragma unroll
                for (int k = 0; k < K; ++k) {
                    const float wk  = wrow[k];                   // broadcast
                    const int   row = (int)cr[k];                // broadcast
                    float4 v = xo4[row * (XO_PITCH / 4) + lane]; // conflict-free
                    o.x = __fmaf_rn(wk, v.x, o.x);
                    o.y = __fmaf_rn(wk, v.y, o.y);
                    o.z = __fmaf_rn(wk, v.z, o.z);
                    o.w = __fmaf_rn(wk, v.w, o.w);
                }
                const int c0 = lane * 4;
                stg[stg_off(c0 + 0, pl)] = o.x;   // conflict-free writes
                stg[stg_off(c0 + 1, pl)] = o.y;
                stg[stg_off(c0 + 2, pl)] = o.z;
                stg[stg_off(c0 + 3, pl)] = o.w;
            }
            __syncthreads();
            // coalesced store: warp = 32 consecutive pixels at fixed channel
            #pragma unroll
            for (int t = 0; t < 8; ++t) {
                const int idx = t * 1024 + tid;
                const int c  = idx >> 6;
                const int pl = idx & 63;
                const int n2 = g * 64 + pl;
                const int i = n2 >> 4, j = n2 & 15;
                out[gbase + c * (112 * 112) + i * 112 + j] = stg[stg_off(c, pl)];
            }
            __syncthreads();
        }
    }
}

extern "C" void kernel_launch(void* const* d_in, const int* in_sizes, int n_in,
                              void* d_out, int out_size) {
    const float* x_in = (const float*)d_in[0];
    const float* f_w  = (const float*)d_in[1];
    const float* f_b  = (const float*)d_in[2];
    const float* ea   = (const float*)d_in[3];
    const float* eb   = (const float*)d_in[4];
    float* out = (float*)d_out;

    cudaFuncSetAttribute(gnn_local_cluster_kernel,
                         cudaFuncAttributeMaxDynamicSharedMemorySize, SMEM_BYTES);
    gnn_local_cluster_kernel<<<196, TPB, SMEM_BYTES>>>(x_in, f_w, f_b, ea, eb, out);
}

// round 12
// speedup vs baseline: 1.0415x; 1.0415x over previous
#include <cuda_runtime.h>
#include <cstdint>

// Problem constants
constexpr int C  = 128;
constexpr int CF = 16;
constexpr int N  = 256;
constexpr int K  = 15;

// ---------------- global scratch (static __device__ — no runtime alloc) ----
__device__ float         g_feat[196 * 256 * 20];   // pre-norm feats (+grid, pads)
__device__ float         g_xnf [196 * 256 * 20];   // normalized feats
__device__ double        g_invn[196 * 256];        // fp64 1/norm
__device__ float         g_w   [196 * 256 * 16];   // softmax weights (15 + pad)
__device__ unsigned char g_rows[196 * 256 * 16];   // neighbor rows  (15 + pad)

// monotone float<->u32 (order-preserving)
__device__ __forceinline__ uint32_t fmono(float f) {
    uint32_t b = __float_as_uint(f);
    return (b & 0x80000000u) ? ~b : (b | 0x80000000u);
}
// monotone double<->u64
__device__ __forceinline__ uint64_t dmono(double d) {
    uint64_t b = (uint64_t)__double_as_longlong(d);
    return (b & 0x8000000000000000ull) ? ~b : (b | 0x8000000000000000ull);
}
__device__ __forceinline__ double dunmono(uint64_t u) {
    uint64_t b = (u & 0x8000000000000000ull) ? (u & 0x7FFFFFFFFFFFFFFFull) : ~u;
    return __longlong_as_double((long long)b);
}

// staging swizzle: conflict-free for channel-lane writes AND pixel-lane reads
__device__ __forceinline__ int stg_off(int c, int px) {
    return c * 64 + ((px + (c >> 2) + 8 * (c & 3)) & 63);
}

// ============================ K1: features =================================
// grid 196, TPB 512, thread = (pixel n, half h). Conv reads x_in directly.
__global__ void __launch_bounds__(512, 2)
k1_features(const float* __restrict__ x_in,
            const float* __restrict__ f_w,
            const float* __restrict__ f_b)
{
    __shared__ float fw[CF * C];     // 8 KB
    __shared__ float fb[CF];
    __shared__ float ex[N * 20];     // 20 KB conv exchange

    const int p   = blockIdx.x;
    const int b   = p / 49;
    const int wg  = (p / 7) % 7;
    const int hg  = p % 7;
    const int tid = threadIdx.x;
    const int n   = tid & 255;
    const int h   = tid >> 8;
    const int gbase = ((b * C * 112) + wg * 16) * 112 + hg * 16;

    for (int idx = tid; idx < CF * C; idx += 512) fw[idx] = f_w[idx];
    if (tid < CF) fb[tid] = f_b[tid];
    __syncthreads();

    // conv: channels h*8..h*8+7 of pixel n; c ascending, FMA from 0, bias after
    {
        float acc[8];
        #pragma unroll
        for (int d = 0; d < 8; ++d) acc[d] = 0.0f;
        const float* xp  = x_in + gbase + (n >> 4) * 112 + (n & 15);
        const float* fwh = fw + h * 8 * C;
        #pragma unroll 4
        for (int c = 0; c < C; ++c) {
            float xv = __ldg(xp + c * 12544);
            #pragma unroll
            for (int d = 0; d < 8; ++d)
                acc[d] = __fmaf_rn(xv, fwh[d * C + c], acc[d]);
        }
        #pragma unroll
        for (int d = 0; d < 8; ++d)
            ex[n * 20 + h * 8 + d] = __fadd_rn(acc[d], fb[h * 8 + d]);
    }
    __syncthreads();

    if (h == 0) {
        const int i = n >> 4, j = n & 15;
        const float sd    = __fsqrt_rn(__fdiv_rn(5440.0f, 255.0f));
        const float denom = __fadd_rn(sd, 1e-5f);
        const float g0 = __fdiv_rn((float)i - 7.5f, denom);
        const float g1 = __fdiv_rn((float)j - 7.5f, denom);
        float* ar = ex + n * 20;
        ar[16] = g0; ar[17] = g1;

        double ss = 0.0;
        #pragma unroll
        for (int d = 0; d < CF; ++d) ss = fma((double)ar[d], (double)ar[d], ss);
        ss = fma((double)g0, (double)g0, ss);
        ss = fma((double)g1, (double)g1, ss);
        double nd = sqrt(ss);
        if (nd < 1e-8) nd = 1e-8;
        double inv = 1.0 / nd;
        g_invn[p * 256 + n] = inv;
        const float rinv = (float)inv;

        float* gf = g_feat + (p * 256 + n) * 20;
        float* gx = g_xnf  + (p * 256 + n) * 20;
        #pragma unroll
        for (int d = 0; d < 18; ++d) { gf[d] = ar[d]; gx[d] = ar[d] * rinv; }
        gf[18] = 0.f; gf[19] = 0.f; gx[18] = 0.f; gx[19] = 0.f;
    }
}

// ============================ K2: edges ====================================
// grid 784 (patch-quarter of 64 rows), TPB 512, thread = (e 0..7, rr 0..63).
constexpr int K2_OFF_XNF = 0;                        // 256*20*4 = 20480
constexpr int K2_OFF_ACC = 20480;                    // 20480
constexpr int K2_OFF_INV = 40960;                    // 256*8 = 2048
constexpr int K2_OFF_BUF = 43008;                    // 8*64*17*4 = 34816 (u64-aligned)
constexpr int K2_OFF_CAND = 77824;                   // 64*20 = 1280
constexpr int K2_SMEM = 79104;

__global__ void __launch_bounds__(512, 2)
k2_edges(const float* __restrict__ edge_alpha,
         const float* __restrict__ edge_beta)
{
    extern __shared__ char smraw[];
    float*    xnf  = reinterpret_cast<float*>(smraw + K2_OFF_XNF);   // [256][20]
    float*    accf = reinterpret_cast<float*>(smraw + K2_OFF_ACC);   // [256][20]
    double*   invd = reinterpret_cast<double*>(smraw + K2_OFF_INV);  // [256]
    uint32_t* bufU = reinterpret_cast<uint32_t*>(smraw + K2_OFF_BUF);// [8][64][17]
    uint64_t* simk = reinterpret_cast<uint64_t*>(smraw + K2_OFF_BUF);// [64][18] (reuse)
    uint8_t*  cand = reinterpret_cast<uint8_t*>(smraw + K2_OFF_CAND);// [64][20]

    const int pp   = blockIdx.x >> 2;
    const int rblk = blockIdx.x & 3;
    const int tid  = threadIdx.x;
    const int rr   = tid & 63;       // row within quarter
    const int e    = tid >> 6;       // candidate-block id (0..7)
    const int n    = rblk * 64 + rr; // row within patch

    // load patch features from scratch (coalesced float4)
    {
        const float4* gx4 = reinterpret_cast<const float4*>(g_xnf  + pp * 5120);
        const float4* gf4 = reinterpret_cast<const float4*>(g_feat + pp * 5120);
        float4* sx4 = reinterpret_cast<float4*>(xnf);
        float4* sa4 = reinterpret_cast<float4*>(accf);
        for (int idx = tid; idx < 1280; idx += 512) { sx4[idx] = gx4[idx]; sa4[idx] = gf4[idx]; }
        if (tid < 256) invd[tid] = g_invn[pp * 256 + tid];
    }
    __syncthreads();

    // ---- pass 1: row n vs candidates [e*32, e*32+32), packed top-16 ----
    {
        float rreg[18];
        const float* xr = xnf + n * 20;
        #pragma unroll
        for (int d = 0; d < 18; ++d) rreg[d] = xr[d];

        uint32_t kb[16];
        #pragma unroll
        for (int k = 0; k < 16; ++k) kb[k] = 0;

        const int mbase = e * 32;
        for (int mm = 0; mm < 32; ++mm) {
            const int m = mbase + mm;
            const float4* xm4 = reinterpret_cast<const float4*>(xnf + m * 20);
            float4 v0 = xm4[0], v1 = xm4[1], v2 = xm4[2], v3 = xm4[3];  // broadcast
            float2 v4 = *reinterpret_cast<const float2*>(xnf + m * 20 + 16);
            float s0 = 0.f, s1 = 0.f, s2 = 0.f, s3 = 0.f;
            s0 = __fmaf_rn(rreg[0],  v0.x, s0); s1 = __fmaf_rn(rreg[1],  v0.y, s1);
            s2 = __fmaf_rn(rreg[2],  v0.z, s2); s3 = __fmaf_rn(rreg[3],  v0.w, s3);
            s0 = __fmaf_rn(rreg[4],  v1.x, s0); s1 = __fmaf_rn(rreg[5],  v1.y, s1);
            s2 = __fmaf_rn(rreg[6],  v1.z, s2); s3 = __fmaf_rn(rreg[7],  v1.w, s3);
            s0 = __fmaf_rn(rreg[8],  v2.x, s0); s1 = __fmaf_rn(rreg[9],  v2.y, s1);
            s2 = __fmaf_rn(rreg[10], v2.z, s2); s3 = __fmaf_rn(rreg[11], v2.w, s3);
            s0 = __fmaf_rn(rreg[12], v3.x, s0); s1 = __fmaf_rn(rreg[13], v3.y, s1);
            s2 = __fmaf_rn(rreg[14], v3.z, s2); s3 = __fmaf_rn(rreg[15], v3.w, s3);
            s0 = __fmaf_rn(rreg[16], v4.x, s0); s1 = __fmaf_rn(rreg[17], v4.y, s1);
            float s = __fadd_rn(__fadd_rn(s0, s1), __fadd_rn(s2, s3));

            uint32_t key = (fmono(s) & 0xFFFFFF00u) | (uint32_t)(255 - m);
            if (key > kb[15]) {
                uint32_t v = key;
                #pragma unroll
                for (int k = 0; k < 16; ++k) {
                    uint32_t mx = (v > kb[k]) ? v : kb[k];
                    uint32_t mn = (v > kb[k]) ? kb[k] : v;
                    kb[k] = mx; v = mn;
                }
            }
        }
        uint32_t* br = bufU + e * (64 * 17) + rr * 17;
        #pragma unroll
        for (int k = 0; k < 16; ++k) br[k] = kb[k];
    }
    __syncthreads();

    // ---- stage A (e<4): merge blocks (2e,2e+1) -> top-16 into slot 2e ----
    if (e < 4) {
        const uint32_t* pa = bufU + (2 * e)     * (64 * 17) + rr * 17;
        const uint32_t* pb = bufU + (2 * e + 1) * (64 * 17) + rr * 17;
        uint32_t outk[16];
        int ia = 0, ib = 0;
        #pragma unroll
        for (int k = 0; k < 16; ++k) {          // ia,ib <= 15
            uint32_t va = pa[ia], vb = pb[ib];
            bool ta = (va >= vb);
            outk[k] = ta ? va : vb;
            ia += ta; ib += !ta;
        }
        uint32_t* po = bufU + (2 * e) * (64 * 17) + rr * 17;
        #pragma unroll
        for (int k = 0; k < 16; ++k) po[k] = outk[k];
    }
    __syncthreads();

    // ---- stage B (e<2): merge slots (4e, 4e+2) -> top-17 into slot 4e ----
    if (e < 2) {
        const uint32_t* pa = bufU + (4 * e)     * (64 * 17) + rr * 17;
        const uint32_t* pb = bufU + (4 * e + 2) * (64 * 17) + rr * 17;
        uint32_t outk[17];
        int ia = 0, ib = 0;
        #pragma unroll
        for (int k = 0; k < 17; ++k) {
            uint32_t va = (ia < 16) ? pa[ia] : 0u;
            uint32_t vb = (ib < 16) ? pb[ib] : 0u;
            bool ta = (va >= vb);
            outk[k] = ta ? va : vb;
            ia += ta; ib += !ta;
        }
        uint32_t* po = bufU + (4 * e) * (64 * 17) + rr * 17;
        #pragma unroll
        for (int k = 0; k < 17; ++k) po[k] = outk[k];
    }
    __syncthreads();

    // ---- stage C (e==0): merge slots (0,4) -> 18-candidate superset ----
    if (e == 0) {
        const uint32_t* pa = bufU + 0 * (64 * 17) + rr * 17;
        const uint32_t* pb = bufU + 4 * (64 * 17) + rr * 17;
        uint8_t outc[18];
        int ia = 0, ib = 0;
        #pragma unroll
        for (int k = 0; k < 18; ++k) {
            uint32_t va = (ia < 17) ? pa[ia] : 0u;
            uint32_t vb = (ib < 17) ? pb[ib] : 0u;
            bool ta = (va >= vb);
            uint32_t v = ta ? va : vb;
            outc[k] = (uint8_t)(255u - (v & 0xFFu));
            ia += ta; ib += !ta;
        }
        uint8_t* cr = cand + rr * 20;
        #pragma unroll
        for (int k = 0; k < 18; ++k) cr[k] = outc[k];
    }
    __syncthreads();   // bufU dead; simk region live

    // ---- df64 rerank: threads e<6 do candidates e*3..e*3+2 ----
    if (e < 6) {
        float ra[20];
        {
            const float4* ar4 = reinterpret_cast<const float4*>(accf + n * 20);
            #pragma unroll
            for (int qq = 0; qq < 5; ++qq)
                reinterpret_cast<float4*>(ra)[qq] = ar4[qq];
        }
        const double inv_n = invd[n];
        const uint8_t* cr = cand + rr * 20;

        #pragma unroll
        for (int tt = 0; tt < 3; ++tt) {
            const int t = e * 3 + tt;
            const int m = (int)cr[t];
            float am[20];
            {
                const float4* am4 = reinterpret_cast<const float4*>(accf + m * 20);
                #pragma unroll
                for (int qq = 0; qq < 5; ++qq)
                    reinterpret_cast<float4*>(am)[qq] = am4[qq];
            }
            // Dot2 (compensated fp32 dot)
            float sh = 0.0f, sl = 0.0f;
            #pragma unroll
            for (int d = 0; d < 18; ++d) {
                float av = ra[d], bv = am[d];
                float ph = __fmul_rn(av, bv);
                float pl = __fmaf_rn(av, bv, -ph);
                float t1 = __fadd_rn(sh, ph);
                float zz = __fsub_rn(t1, sh);
                float ee = __fadd_rn(__fsub_rn(sh, __fsub_rn(t1, zz)),
                                     __fsub_rn(ph, zz));
                sh = t1;
                sl = __fadd_rn(sl, __fadd_rn(ee, pl));
            }
            double sim = ((double)sh + (double)sl) * inv_n * invd[m];
            simk[rr * 18 + t] = (dmono(sim) & ~0xFFull) | (uint64_t)(255 - m);
        }
    }
    __syncthreads();

    // ---- top-15 select + sigmoid/softmax (e==0) ----
    if (e == 0) {
        const uint64_t* sr = simk + rr * 18;
        uint64_t top[K];
        #pragma unroll
        for (int k = 0; k < K; ++k) top[k] = 0;
        #pragma unroll
        for (int t = 0; t < 18; ++t) {
            uint64_t u = sr[t];
            if (u > top[K - 1]) {
                #pragma unroll
                for (int k = 0; k < K; ++k) {
                    uint64_t mx = (u > top[k]) ? u : top[k];
                    uint64_t mn = (u > top[k]) ? top[k] : u;
                    top[k] = mx; u = mn;
                }
            }
        }
        float sims[K]; int rows[K];
        #pragma unroll
        for (int k = 0; k < K; ++k) {
            rows[k] = 255 - (int)(top[k] & 0xFFull);
            sims[k] = (float)dunmono((top[k] & ~0xFFull) | 0x80ull);
        }

        const float alpha = edge_alpha[0];
        const float beta  = edge_beta[0];
        float wn_[K];
        float wmax = -1e30f;
        #pragma unroll
        for (int k = 0; k < K; ++k) {
            float z  = __fadd_rn(beta, __fmul_rn(alpha, sims[k]));
            float wv = __fdiv_rn(1.0f, __fadd_rn(1.0f, expf(-z)));
            wn_[k] = wv;
            wmax = fmaxf(wmax, wv);
        }
        float wsum = 0.0f;
        #pragma unroll
        for (int k = 0; k < K; ++k) {
            wn_[k] = expf(__fadd_rn(wn_[k], -wmax));
            wsum = __fadd_rn(wsum, wn_[k]);
        }
        float*         wp = g_w    + (pp * 256 + n) * 16;
        unsigned char* rp = g_rows + (pp * 256 + n) * 16;
        #pragma unroll
        for (int k = 0; k < K; ++k) {
            wp[k] = __fdiv_rn(wn_[k], wsum);
            rp[k] = (unsigned char)rows[k];
        }
        wp[15] = 0.f; rp[15] = 0;
    }
}

// ============================ K3: gather ===================================
constexpr int XO_PITCH = 132;
constexpr int K3_OFF_XO  = 0;                       // 256*132*4 = 135168
constexpr int K3_OFF_WR  = 135168;                  // 256*16*4  = 16384
constexpr int K3_OFF_RW  = 151552;                  // 256*16    = 4096
constexpr int K3_OFF_STG = 155648;                  // 128*64*4  = 32768
constexpr int K3_SMEM = 188416;

__global__ void __launch_bounds__(1024, 1)
k3_gather(const float* __restrict__ x_in, float* __restrict__ out)
{
    extern __shared__ char smraw[];
    float*    xo = reinterpret_cast<float*>(smraw + K3_OFF_XO);   // [256][132]
    float*    wr = reinterpret_cast<float*>(smraw + K3_OFF_WR);   // [256][16]
    uint8_t*  rw = reinterpret_cast<uint8_t*>(smraw + K3_OFF_RW); // [256][16]
    float*    stg = reinterpret_cast<float*>(smraw + K3_OFF_STG); // [128][64]

    const int p   = blockIdx.x;
    const int b   = p / 49;
    const int wg  = (p / 7) % 7;
    const int hg  = p % 7;
    const int tid = threadIdx.x;
    const int gbase = ((b * C * 112) + wg * 16) * 112 + hg * 16;

    // load patch tile + weights/rows
    for (int idx = tid; idx < C * N; idx += 1024) {
        int c = idx >> 8;
        int nn = idx & 255;
        int i = nn >> 4, j = nn & 15;
        xo[nn * XO_PITCH + c] = x_in[gbase + c * 12544 + i * 112 + j];
    }
    for (int idx = tid; idx < 4096; idx += 1024) wr[idx] = g_w[p * 4096 + idx];
    {
        const uint32_t* gr32 = reinterpret_cast<const uint32_t*>(g_rows);
        uint32_t* rw32 = reinterpret_cast<uint32_t*>(rw);
        if (tid < 1024) rw32[tid] = gr32[p * 1024 + tid];
    }
    __syncthreads();

    const int wid  = tid >> 5;
    const int lane = tid & 31;
    const float4* xo4 = reinterpret_cast<const float4*>(xo);

    #pragma unroll 1
    for (int g = 0; g < 4; ++g) {
        #pragma unroll
        for (int px = 0; px < 2; ++px) {
            const int pl = wid * 2 + px;        // 0..63
            const int n2 = g * 64 + pl;
            const float*   wrow = wr + n2 * 16;
            const uint8_t* cr   = rw + n2 * 16;
            float4 o = make_float4(0.f, 0.f, 0.f, 0.f);
            #pragma unroll
            for (int k = 0; k < K; ++k) {
                const float wk  = wrow[k];                   // broadcast
                const int   row = (int)cr[k];                // broadcast
                float4 v = xo4[row * (XO_PITCH / 4) + lane]; // conflict-free
                o.x = __fmaf_rn(wk, v.x, o.x);
                o.y = __fmaf_rn(wk, v.y, o.y);
                o.z = __fmaf_rn(wk, v.z, o.z);
                o.w = __fmaf_rn(wk, v.w, o.w);
            }
            const int c0 = lane * 4;
            stg[stg_off(c0 + 0, pl)] = o.x;
            stg[stg_off(c0 + 1, pl)] = o.y;
            stg[stg_off(c0 + 2, pl)] = o.z;
            stg[stg_off(c0 + 3, pl)] = o.w;
        }
        __syncthreads();
        #pragma unroll
        for (int t = 0; t < 8; ++t) {
            const int idx = t * 1024 + tid;
            const int c  = idx >> 6;
            const int pl = idx & 63;
            const int n2 = g * 64 + pl;
            const int i = n2 >> 4, j = n2 & 15;
            out[gbase + c * 12544 + i * 112 + j] = stg[stg_off(c, pl)];
        }
        __syncthreads();
    }
}

// ============================ launch =======================================
extern "C" void kernel_launch(void* const* d_in, const int* in_sizes, int n_in,
                              void* d_out, int out_size) {
    const float* x_in = (const float*)d_in[0];
    const float* f_w  = (const float*)d_in[1];
    const float* f_b  = (const float*)d_in[2];
    const float* ea   = (const float*)d_in[3];
    const float* eb   = (const float*)d_in[4];
    float* out = (float*)d_out;

    cudaFuncSetAttribute(k2_edges,
                         cudaFuncAttributeMaxDynamicSharedMemorySize, K2_SMEM);
    cudaFuncSetAttribute(k3_gather,
                         cudaFuncAttributeMaxDynamicSharedMemorySize, K3_SMEM);

    k1_features<<<196, 512>>>(x_in, f_w, f_b);
    k2_edges<<<784, 512, K2_SMEM>>>(ea, eb);
    k3_gather<<<196, 1024, K3_SMEM>>>(x_in, out);
}